// round 1
// baseline (speedup 1.0000x reference)
#include <cuda_runtime.h>
#include <cstddef>

// Problem constants
#define B_  2
#define S_  2048
#define D_  2048
#define H_  16
#define HD_ 128

// Scratch (allocation-free: __device__ globals)
__device__ float g_qkv[(size_t)B_ * S_ * 3 * D_];   // [B,S,3D] = 100.7 MB
__device__ float g_attn[(size_t)B_ * S_ * D_];      // [B,S,D]  = 33.6 MB

// ---------------------------------------------------------------------------
// Kernel 1/3: tiled fp32 GEMM with fused bias.  C[M,N] = A[M,K] @ B[K,N] + bias
// BM=BN=128, BK=8, 256 threads, 8x8 per-thread micro-tile.
// ---------------------------------------------------------------------------
__global__ __launch_bounds__(256) void sgemm_bias(
    const float* __restrict__ A, const float* __restrict__ Bm,
    const float* __restrict__ bias, float* __restrict__ C,
    int M, int N, int K)
{
    __shared__ float As[8][128];
    __shared__ float Bs[8][128];

    const int tid = threadIdx.x;
    const int bn = blockIdx.x;   // N tile
    const int bm = blockIdx.y;   // M tile

    const float* Ab = A + (size_t)bm * 128 * K;
    const float* Bb = Bm + (size_t)bn * 128;

    const int aRow = tid >> 1;          // 0..127
    const int aCol = (tid & 1) * 4;     // 0 or 4
    const int bRow = tid >> 5;          // 0..7
    const int bCol = (tid & 31) * 4;    // 0..124
    const int ty = tid >> 4;            // 0..15
    const int tx = tid & 15;            // 0..15

    float acc[8][8];
    #pragma unroll
    for (int i = 0; i < 8; i++)
        #pragma unroll
        for (int j = 0; j < 8; j++) acc[i][j] = 0.f;

    for (int k0 = 0; k0 < K; k0 += 8) {
        float4 a4 = *(const float4*)(Ab + (size_t)aRow * K + k0 + aCol);
        As[aCol + 0][aRow] = a4.x;
        As[aCol + 1][aRow] = a4.y;
        As[aCol + 2][aRow] = a4.z;
        As[aCol + 3][aRow] = a4.w;
        *(float4*)(&Bs[bRow][bCol]) =
            *(const float4*)(Bb + (size_t)(k0 + bRow) * N + bCol);
        __syncthreads();

        #pragma unroll
        for (int kk = 0; kk < 8; kk++) {
            float4 a0 = *(float4*)(&As[kk][ty * 8]);
            float4 a1 = *(float4*)(&As[kk][ty * 8 + 4]);
            float4 b0 = *(float4*)(&Bs[kk][tx * 8]);
            float4 b1 = *(float4*)(&Bs[kk][tx * 8 + 4]);
            float ar[8] = {a0.x, a0.y, a0.z, a0.w, a1.x, a1.y, a1.z, a1.w};
            float br[8] = {b0.x, b0.y, b0.z, b0.w, b1.x, b1.y, b1.z, b1.w};
            #pragma unroll
            for (int i = 0; i < 8; i++)
                #pragma unroll
                for (int j = 0; j < 8; j++)
                    acc[i][j] += ar[i] * br[j];
        }
        __syncthreads();
    }

    #pragma unroll
    for (int i = 0; i < 8; i++) {
        size_t row = (size_t)bm * 128 + ty * 8 + i;
        #pragma unroll
        for (int j = 0; j < 8; j += 4) {
            int col = bn * 128 + tx * 8 + j;
            float4 bv = *(const float4*)(bias + col);
            float4 o;
            o.x = acc[i][j + 0] + bv.x;
            o.y = acc[i][j + 1] + bv.y;
            o.z = acc[i][j + 2] + bv.z;
            o.w = acc[i][j + 3] + bv.w;
            *(float4*)(C + row * N + col) = o;
        }
    }
}

// ---------------------------------------------------------------------------
// Kernel 2/3: causal flash attention, fp32, online softmax.
// Grid: (S/64, H, B).  256 threads.  64-query x 64-key tiles, HD=128.
// qkv layout per GEMM1 output: qkv[b][s][h*384 + t], t<128:q, 128..255:k, 256..383:v
// ---------------------------------------------------------------------------
#define BQ  64
#define BKV 64
#define QS_STRIDE 132
#define KS_STRIDE 129   // odd-ish stride => score-phase K reads <=2-way conflicted
#define VS_STRIDE 132
#define PS_STRIDE 65    // conflict-free row access

#define FLASH_SMEM_FLOATS (BQ*QS_STRIDE + BKV*KS_STRIDE + BKV*VS_STRIDE + BQ*PS_STRIDE + 3*BQ)
#define FLASH_SMEM_BYTES  (FLASH_SMEM_FLOATS * 4)

__global__ __launch_bounds__(256) void flash_attn(
    const float* __restrict__ qkv, float* __restrict__ out)
{
    extern __shared__ float smem[];
    float* Qs = smem;                        // [BQ][132]
    float* Ks = Qs + BQ * QS_STRIDE;         // [BKV][129]
    float* Vs = Ks + BKV * KS_STRIDE;        // [BKV][132]
    float* Ps = Vs + BKV * VS_STRIDE;        // [BQ][65]
    float* m_s = Ps + BQ * PS_STRIDE;
    float* l_s = m_s + BQ;
    float* alpha_s = l_s + BQ;

    const int tid = threadIdx.x;
    const int h = blockIdx.y, b = blockIdx.z;
    const int q0 = blockIdx.x * BQ;
    const float* base = qkv + (size_t)b * S_ * (3 * D_) + (size_t)h * (3 * HD_);

    // Load Q tile [BQ][HD]
    for (int i = tid; i < BQ * HD_ / 4; i += 256) {
        int r = i >> 5;           // HD_/4 == 32
        int c = (i & 31) << 2;
        float4 v = *(const float4*)(base + (size_t)(q0 + r) * (3 * D_) + c);
        *(float4*)(&Qs[r * QS_STRIDE + c]) = v;
    }
    if (tid < BQ) { m_s[tid] = -1e30f; l_s[tid] = 0.f; }

    float o[32];
    #pragma unroll
    for (int i = 0; i < 32; i++) o[i] = 0.f;
    const int orow  = tid & 63;
    const int obase = (tid >> 6) << 5;
    const int warp  = tid >> 5;
    const int lane  = tid & 31;
    __syncthreads();

    const float scale = 0.08838834764831845f;  // 1/sqrt(128)
    const int nkt = blockIdx.x + 1;             // causal: only tiles up to diagonal

    for (int kt = 0; kt < nkt; kt++) {
        const int k0 = kt * BKV;

        // Load K,V tiles
        for (int i = tid; i < BKV * HD_ / 4; i += 256) {
            int r = i >> 5;
            int c = (i & 31) << 2;
            const float* kp = base + (size_t)(k0 + r) * (3 * D_) + HD_ + c;
            float4 kv = *(const float4*)(kp);
            float4 vv = *(const float4*)(kp + HD_);
            Ks[r * KS_STRIDE + c + 0] = kv.x;
            Ks[r * KS_STRIDE + c + 1] = kv.y;
            Ks[r * KS_STRIDE + c + 2] = kv.z;
            Ks[r * KS_STRIDE + c + 3] = kv.w;
            *(float4*)(&Vs[r * VS_STRIDE + c]) = vv;
        }
        __syncthreads();

        // Scores: warp handles rows warp*8..+7; lane handles cols lane, lane+32
        float s0[8], s1[8];
        #pragma unroll
        for (int i = 0; i < 8; i++) { s0[i] = 0.f; s1[i] = 0.f; }
        #pragma unroll 4
        for (int d = 0; d < HD_; d++) {
            float ka = Ks[lane * KS_STRIDE + d];
            float kb = Ks[(lane + 32) * KS_STRIDE + d];
            #pragma unroll
            for (int i = 0; i < 8; i++) {
                float q = Qs[(warp * 8 + i) * QS_STRIDE + d];
                s0[i] += q * ka;
                s1[i] += q * kb;
            }
        }

        const bool diag = (kt == nkt - 1);  // only diagonal tile needs masking
        #pragma unroll
        for (int i = 0; i < 8; i++) {
            int qr = q0 + warp * 8 + i;
            float v0 = s0[i] * scale, v1 = s1[i] * scale;
            if (diag) {
                if (k0 + lane > qr)      v0 = -1e30f;
                if (k0 + lane + 32 > qr) v1 = -1e30f;
            }
            Ps[(warp * 8 + i) * PS_STRIDE + lane]      = v0;
            Ps[(warp * 8 + i) * PS_STRIDE + lane + 32] = v1;
        }
        __syncthreads();

        // Online softmax: thread per row
        if (tid < BQ) {
            float mold = m_s[tid];
            float mnew = mold;
            float* pw = Ps + tid * PS_STRIDE;
            #pragma unroll 8
            for (int j = 0; j < BKV; j++) mnew = fmaxf(mnew, pw[j]);
            float alpha = __expf(mold - mnew);
            float lsum = 0.f;
            #pragma unroll 8
            for (int j = 0; j < BKV; j++) {
                float p = __expf(pw[j] - mnew);
                pw[j] = p;
                lsum += p;
            }
            m_s[tid] = mnew;
            l_s[tid] = l_s[tid] * alpha + lsum;
            alpha_s[tid] = alpha;
        }
        __syncthreads();

        // O update: thread owns (row=orow, dims obase..obase+31)
        float alpha = alpha_s[orow];
        #pragma unroll
        for (int dd = 0; dd < 32; dd++) o[dd] *= alpha;
        #pragma unroll 2
        for (int j = 0; j < BKV; j++) {
            float p = Ps[orow * PS_STRIDE + j];
            const float* vrow = Vs + j * VS_STRIDE + obase;
            #pragma unroll
            for (int dd = 0; dd < 32; dd += 4) {
                float4 v = *(const float4*)(vrow + dd);
                o[dd + 0] += p * v.x;
                o[dd + 1] += p * v.y;
                o[dd + 2] += p * v.z;
                o[dd + 3] += p * v.w;
            }
        }
        __syncthreads();
    }

    const float inv_l = 1.0f / l_s[orow];
    float* op = out + (size_t)(b * S_ + q0 + orow) * D_ + h * HD_ + obase;
    #pragma unroll
    for (int dd = 0; dd < 32; dd += 4) {
        float4 v;
        v.x = o[dd + 0] * inv_l;
        v.y = o[dd + 1] * inv_l;
        v.z = o[dd + 2] * inv_l;
        v.w = o[dd + 3] * inv_l;
        *(float4*)(op + dd) = v;
    }
}

// ---------------------------------------------------------------------------
// Launch: QKV GEMM -> flash attention -> output GEMM
// Inputs (metadata order): x, Wqkv, bqkv, Wo, bo.  Output: [B,S,D] fp32.
// ---------------------------------------------------------------------------
extern "C" void kernel_launch(void* const* d_in, const int* in_sizes, int n_in,
                              void* d_out, int out_size)
{
    (void)in_sizes; (void)n_in; (void)out_size;
    const float* x    = (const float*)d_in[0];
    const float* Wqkv = (const float*)d_in[1];
    const float* bqkv = (const float*)d_in[2];
    const float* Wo   = (const float*)d_in[3];
    const float* bo   = (const float*)d_in[4];
    float* out = (float*)d_out;

    float *qkv_ptr = nullptr, *attn_ptr = nullptr;
    cudaGetSymbolAddress((void**)&qkv_ptr, g_qkv);
    cudaGetSymbolAddress((void**)&attn_ptr, g_attn);

    cudaFuncSetAttribute(flash_attn,
                         cudaFuncAttributeMaxDynamicSharedMemorySize,
                         FLASH_SMEM_BYTES);

    const int M = B_ * S_;       // 4096
    // 1) qkv = x @ Wqkv + bqkv     [4096, 6144]
    sgemm_bias<<<dim3((3 * D_) / 128, M / 128), 256>>>(
        x, Wqkv, bqkv, qkv_ptr, M, 3 * D_, D_);
    // 2) flash attention -> g_attn [B,S,D]
    flash_attn<<<dim3(S_ / BQ, H_, B_), 256, FLASH_SMEM_BYTES>>>(qkv_ptr, attn_ptr);
    // 3) out = attn @ Wo + bo      [4096, 2048]
    sgemm_bias<<<dim3(D_ / 128, M / 128), 256>>>(
        attn_ptr, Wo, bo, out, M, D_, D_);
}

// round 3
// speedup vs baseline: 1.6094x; 1.6094x over previous
#include <cuda_runtime.h>
#include <cuda_bf16.h>
#include <cstdint>
#include <cstddef>

// ---------------------------------------------------------------------------
// Problem constants
// ---------------------------------------------------------------------------
#define B_  2
#define S_  2048
#define D_  2048
#define H_  16
#define HD_ 128
#define M_  (B_*S_)            // 4096 rows

// ---------------------------------------------------------------------------
// Scratch (__device__ globals; no allocation allowed)
// ---------------------------------------------------------------------------
__device__ float g_qkv[(size_t)M_ * 3 * D_];                        // 100.7 MB
__device__ __nv_bfloat16 g_xhi[(size_t)M_ * D_];
__device__ __nv_bfloat16 g_xlo[(size_t)M_ * D_];
__device__ __nv_bfloat16 g_w1hi[(size_t)3 * D_ * D_];               // Wqkv^T [6144,2048]
__device__ __nv_bfloat16 g_w1lo[(size_t)3 * D_ * D_];
__device__ __nv_bfloat16 g_w2hi[(size_t)D_ * D_];                   // Wo^T [2048,2048]
__device__ __nv_bfloat16 g_w2lo[(size_t)D_ * D_];
__device__ __nv_bfloat16 g_ahi[(size_t)M_ * D_];                    // attention out hi
__device__ __nv_bfloat16 g_alo[(size_t)M_ * D_];

// ---------------------------------------------------------------------------
// Portable PTX helpers (NO tcgen05 — virtual arch is compute_103)
// ---------------------------------------------------------------------------
__device__ __forceinline__ uint32_t smem_u32(const void* p) {
    uint32_t a;
    asm("{ .reg .u64 t; cvta.to.shared.u64 t, %1; cvt.u32.u64 %0, t; }"
        : "=r"(a) : "l"(p));
    return a;
}

#define CP16(dst_u32, src_ptr) \
    asm volatile("cp.async.cg.shared.global [%0], [%1], 16;" \
                 :: "r"(dst_u32), "l"(src_ptr) : "memory")
#define CP_COMMIT() asm volatile("cp.async.commit_group;" ::: "memory")
#define CP_WAIT(n)  asm volatile("cp.async.wait_group %0;" :: "n"(n) : "memory")

#define LDSM_X4(r0, r1, r2, r3, addr) \
    asm volatile("ldmatrix.sync.aligned.m8n8.x4.shared.b16 {%0,%1,%2,%3}, [%4];" \
                 : "=r"(r0), "=r"(r1), "=r"(r2), "=r"(r3) : "r"(addr))

__device__ __forceinline__ void mma16816(float* d, const uint32_t* a,
                                         const uint32_t* b) {
    asm volatile(
        "mma.sync.aligned.m16n8k16.row.col.f32.bf16.bf16.f32 "
        "{%0,%1,%2,%3}, {%4,%5,%6,%7}, {%8,%9}, {%0,%1,%2,%3};"
        : "+f"(d[0]), "+f"(d[1]), "+f"(d[2]), "+f"(d[3])
        : "r"(a[0]), "r"(a[1]), "r"(a[2]), "r"(a[3]), "r"(b[0]), "r"(b[1]));
}

// fp32 -> bf16 hi/lo split
__device__ __forceinline__ void split1(float v, __nv_bfloat16& h, __nv_bfloat16& l) {
    h = __float2bfloat16(v);
    l = __float2bfloat16(v - __bfloat162float(h));
}

// ---------------------------------------------------------------------------
// Kernel: fp32 -> (hi,lo) bf16 elementwise split
// ---------------------------------------------------------------------------
__global__ void split_f32(const float* __restrict__ in,
                          __nv_bfloat16* __restrict__ hi,
                          __nv_bfloat16* __restrict__ lo, int n4) {
    int i = blockIdx.x * blockDim.x + threadIdx.x;
    if (i >= n4) return;
    float4 v = *(const float4*)(in + (size_t)i * 4);
    __nv_bfloat16 h0, h1, h2, h3, l0, l1, l2, l3;
    split1(v.x, h0, l0); split1(v.y, h1, l1);
    split1(v.z, h2, l2); split1(v.w, h3, l3);
    __nv_bfloat162* hp = (__nv_bfloat162*)(hi + (size_t)i * 4);
    __nv_bfloat162* lp = (__nv_bfloat162*)(lo + (size_t)i * 4);
    hp[0] = __nv_bfloat162(h0, h1); hp[1] = __nv_bfloat162(h2, h3);
    lp[0] = __nv_bfloat162(l0, l1); lp[1] = __nv_bfloat162(l2, l3);
}

// ---------------------------------------------------------------------------
// Kernel: W[K,N] -> T[N,K] transpose + hi/lo split
// ---------------------------------------------------------------------------
__global__ void transpose_split(const float* __restrict__ W,
                                __nv_bfloat16* __restrict__ Th,
                                __nv_bfloat16* __restrict__ Tl, int K, int N) {
    __shared__ float t[32][33];
    int n0 = blockIdx.x * 32, k0 = blockIdx.y * 32;
    int tx = threadIdx.x, ty = threadIdx.y;      // (32,8)
    #pragma unroll
    for (int j = 0; j < 32; j += 8)
        t[ty + j][tx] = W[(size_t)(k0 + ty + j) * N + n0 + tx];
    __syncthreads();
    #pragma unroll
    for (int j = 0; j < 32; j += 8) {
        float v = t[tx][ty + j];
        __nv_bfloat16 h, l; split1(v, h, l);
        size_t o = (size_t)(n0 + ty + j) * K + k0 + tx;
        Th[o] = h; Tl[o] = l;
    }
}

// ---------------------------------------------------------------------------
// HMMA bf16x3 GEMM:  C[M,N] = A[M,K] @ Bt[N,K]^T + bias
// BM=128, BN=128, BK=32, 256 threads (8 warps, 2x4), cp.async double buffer.
// ---------------------------------------------------------------------------
#define GBK 32
#define LDSB 80                       // bytes per smem row (32 bf16 + 8 pad)
#define TILEB (128 * LDSB)            // 10240 B per matrix tile
#define OFF_AH 0
#define OFF_AL (TILEB)
#define OFF_BH (2 * TILEB)
#define OFF_BL (3 * TILEB)
#define STAGEB (4 * TILEB)            // 40960 B
#define GEMM_DYN_SMEM (2 * STAGEB)

__global__ __launch_bounds__(256, 1) void gemm_bf16x3(
    const __nv_bfloat16* __restrict__ Ah, const __nv_bfloat16* __restrict__ Al,
    const __nv_bfloat16* __restrict__ Bh, const __nv_bfloat16* __restrict__ Bl,
    const float* __restrict__ bias, float* __restrict__ C,
    int M, int N, int K)
{
    extern __shared__ __align__(128) char sm[];
    const uint32_t sbase = smem_u32(sm);

    const int tid = threadIdx.x;
    const int wid = tid >> 5;
    const int lane = tid & 31;
    const int m0 = blockIdx.y * 128;
    const int n0 = blockIdx.x * 128;
    const int wm = (wid >> 2) * 64;    // warp m offset: 0 / 64
    const int wn = (wid & 3) * 32;     // warp n offset: 0/32/64/96

    // ---- producer: 8 cp.async of 16B per thread per stage ----
    const int prow = tid >> 2;         // 0..63
    const int pc = tid & 3;            // 16B chunk in 64B row
    auto produce = [&](int stg, int kblk) {
        uint32_t s = sbase + stg * STAGEB;
        #pragma unroll
        for (int h = 0; h < 2; h++) {
            int r = prow + h * 64;
            uint32_t d = r * LDSB + pc * 16;
            size_t ga = (size_t)(m0 + r) * K + kblk + pc * 8;
            size_t gb = (size_t)(n0 + r) * K + kblk + pc * 8;
            CP16(s + OFF_AH + d, Ah + ga);
            CP16(s + OFF_AL + d, Al + ga);
            CP16(s + OFF_BH + d, Bh + gb);
            CP16(s + OFF_BL + d, Bl + gb);
        }
    };

    float acc[4][4][4];
    #pragma unroll
    for (int i = 0; i < 4; i++)
        #pragma unroll
        for (int j = 0; j < 4; j++)
            #pragma unroll
            for (int r = 0; r < 4; r++) acc[i][j][r] = 0.f;

    // ldmatrix per-lane address components
    const uint32_t a_row = wm + (lane & 15);          // + ti*16
    const uint32_t a_kb  = (lane >> 4) * 16;          // + ks*32
    const uint32_t b_row = wn + (lane & 7) + ((lane >> 4) & 1) * 8;  // + pj*16
    const uint32_t b_kb  = ((lane >> 3) & 1) * 16;    // + ks*32

    auto compute = [&](int stg) {
        uint32_t s = sbase + stg * STAGEB;
        #pragma unroll
        for (int ks = 0; ks < 2; ks++) {
            uint32_t ah[4][4], al[4][4], bh[4][2], bl[4][2];
            #pragma unroll
            for (int ti = 0; ti < 4; ti++) {
                uint32_t ad = s + (a_row + ti * 16) * LDSB + ks * 32 + a_kb;
                LDSM_X4(ah[ti][0], ah[ti][1], ah[ti][2], ah[ti][3], ad + OFF_AH);
                LDSM_X4(al[ti][0], al[ti][1], al[ti][2], al[ti][3], ad + OFF_AL);
            }
            #pragma unroll
            for (int pj = 0; pj < 2; pj++) {
                uint32_t bd = s + (b_row + pj * 16) * LDSB + ks * 32 + b_kb;
                uint32_t r0, r1, r2, r3;
                LDSM_X4(r0, r1, r2, r3, bd + OFF_BH);
                bh[pj * 2][0] = r0; bh[pj * 2][1] = r1;
                bh[pj * 2 + 1][0] = r2; bh[pj * 2 + 1][1] = r3;
                LDSM_X4(r0, r1, r2, r3, bd + OFF_BL);
                bl[pj * 2][0] = r0; bl[pj * 2][1] = r1;
                bl[pj * 2 + 1][0] = r2; bl[pj * 2 + 1][1] = r3;
            }
            #pragma unroll
            for (int ti = 0; ti < 4; ti++)
                #pragma unroll
                for (int tj = 0; tj < 4; tj++) {
                    mma16816(acc[ti][tj], ah[ti], bh[tj]);
                    mma16816(acc[ti][tj], ah[ti], bl[tj]);
                    mma16816(acc[ti][tj], al[ti], bh[tj]);
                }
        }
    };

    const int NK = K / GBK;
    produce(0, 0);
    CP_COMMIT();

    for (int it = 0; it < NK; ++it) {
        if (it + 1 < NK) {
            produce((it + 1) & 1, (it + 1) * GBK);
            CP_COMMIT();
            CP_WAIT(1);
        } else {
            CP_WAIT(0);
        }
        __syncthreads();
        compute(it & 1);
        __syncthreads();
    }

    // ---- epilogue: fragments -> C + bias ----
    const int er = lane >> 2;           // 0..7
    const int ec = (lane & 3) * 2;      // 0,2,4,6
    #pragma unroll
    for (int ti = 0; ti < 4; ti++) {
        #pragma unroll
        for (int tj = 0; tj < 4; tj++) {
            int col = n0 + wn + tj * 8 + ec;
            float bx = bias[col], by = bias[col + 1];
            int row = m0 + wm + ti * 16 + er;
            float2 v0 = { acc[ti][tj][0] + bx, acc[ti][tj][1] + by };
            float2 v1 = { acc[ti][tj][2] + bx, acc[ti][tj][3] + by };
            *(float2*)(C + (size_t)row * N + col) = v0;
            *(float2*)(C + (size_t)(row + 8) * N + col) = v1;
        }
    }
}

// ---------------------------------------------------------------------------
// Causal flash attention, fp32, online softmax.  Writes bf16 hi/lo output.
// Grid: (S/64, H, B).  256 threads.
// ---------------------------------------------------------------------------
#define BQ  64
#define BKV 64
#define QS_STRIDE 132
#define KS_STRIDE 129
#define VS_STRIDE 132
#define PS_STRIDE 65
#define FLASH_SMEM_FLOATS (BQ*QS_STRIDE + BKV*KS_STRIDE + BKV*VS_STRIDE + BQ*PS_STRIDE + 3*BQ)
#define FLASH_SMEM_BYTES  (FLASH_SMEM_FLOATS * 4)

__global__ __launch_bounds__(256) void flash_attn(
    const float* __restrict__ qkv,
    __nv_bfloat16* __restrict__ out_hi, __nv_bfloat16* __restrict__ out_lo)
{
    extern __shared__ float smem[];
    float* Qs = smem;
    float* Ks = Qs + BQ * QS_STRIDE;
    float* Vs = Ks + BKV * KS_STRIDE;
    float* Ps = Vs + BKV * VS_STRIDE;
    float* m_s = Ps + BQ * PS_STRIDE;
    float* l_s = m_s + BQ;
    float* alpha_s = l_s + BQ;

    const int tid = threadIdx.x;
    const int h = blockIdx.y, b = blockIdx.z;
    const int q0 = blockIdx.x * BQ;
    const float* base = qkv + (size_t)b * S_ * (3 * D_) + (size_t)h * (3 * HD_);

    for (int i = tid; i < BQ * HD_ / 4; i += 256) {
        int r = i >> 5;
        int c = (i & 31) << 2;
        float4 v = *(const float4*)(base + (size_t)(q0 + r) * (3 * D_) + c);
        *(float4*)(&Qs[r * QS_STRIDE + c]) = v;
    }
    if (tid < BQ) { m_s[tid] = -1e30f; l_s[tid] = 0.f; }

    float o[32];
    #pragma unroll
    for (int i = 0; i < 32; i++) o[i] = 0.f;
    const int orow  = tid & 63;
    const int obase = (tid >> 6) << 5;
    const int warp  = tid >> 5;
    const int lane  = tid & 31;
    __syncthreads();

    const float scale = 0.08838834764831845f;
    const int nkt = blockIdx.x + 1;

    for (int kt = 0; kt < nkt; kt++) {
        const int k0 = kt * BKV;
        for (int i = tid; i < BKV * HD_ / 4; i += 256) {
            int r = i >> 5;
            int c = (i & 31) << 2;
            const float* kp = base + (size_t)(k0 + r) * (3 * D_) + HD_ + c;
            float4 kv = *(const float4*)(kp);
            float4 vv = *(const float4*)(kp + HD_);
            Ks[r * KS_STRIDE + c + 0] = kv.x;
            Ks[r * KS_STRIDE + c + 1] = kv.y;
            Ks[r * KS_STRIDE + c + 2] = kv.z;
            Ks[r * KS_STRIDE + c + 3] = kv.w;
            *(float4*)(&Vs[r * VS_STRIDE + c]) = vv;
        }
        __syncthreads();

        float s0[8], s1[8];
        #pragma unroll
        for (int i = 0; i < 8; i++) { s0[i] = 0.f; s1[i] = 0.f; }
        #pragma unroll 4
        for (int d = 0; d < HD_; d++) {
            float ka = Ks[lane * KS_STRIDE + d];
            float kb = Ks[(lane + 32) * KS_STRIDE + d];
            #pragma unroll
            for (int i = 0; i < 8; i++) {
                float q = Qs[(warp * 8 + i) * QS_STRIDE + d];
                s0[i] += q * ka;
                s1[i] += q * kb;
            }
        }

        const bool diag = (kt == nkt - 1);
        #pragma unroll
        for (int i = 0; i < 8; i++) {
            int qr = q0 + warp * 8 + i;
            float v0 = s0[i] * scale, v1 = s1[i] * scale;
            if (diag) {
                if (k0 + lane > qr)      v0 = -1e30f;
                if (k0 + lane + 32 > qr) v1 = -1e30f;
            }
            Ps[(warp * 8 + i) * PS_STRIDE + lane]      = v0;
            Ps[(warp * 8 + i) * PS_STRIDE + lane + 32] = v1;
        }
        __syncthreads();

        if (tid < BQ) {
            float mold = m_s[tid];
            float mnew = mold;
            float* pw = Ps + tid * PS_STRIDE;
            #pragma unroll 8
            for (int j = 0; j < BKV; j++) mnew = fmaxf(mnew, pw[j]);
            float alpha = __expf(mold - mnew);
            float lsum = 0.f;
            #pragma unroll 8
            for (int j = 0; j < BKV; j++) {
                float p = __expf(pw[j] - mnew);
                pw[j] = p;
                lsum += p;
            }
            m_s[tid] = mnew;
            l_s[tid] = l_s[tid] * alpha + lsum;
            alpha_s[tid] = alpha;
        }
        __syncthreads();

        float alpha = alpha_s[orow];
        #pragma unroll
        for (int dd = 0; dd < 32; dd++) o[dd] *= alpha;
        #pragma unroll 2
        for (int j = 0; j < BKV; j++) {
            float p = Ps[orow * PS_STRIDE + j];
            const float* vrow = Vs + j * VS_STRIDE + obase;
            #pragma unroll
            for (int dd = 0; dd < 32; dd += 4) {
                float4 v = *(const float4*)(vrow + dd);
                o[dd + 0] += p * v.x;
                o[dd + 1] += p * v.y;
                o[dd + 2] += p * v.z;
                o[dd + 3] += p * v.w;
            }
        }
        __syncthreads();
    }

    const float inv_l = 1.0f / l_s[orow];
    size_t oidx = (size_t)(b * S_ + q0 + orow) * D_ + h * HD_ + obase;
    #pragma unroll
    for (int dd = 0; dd < 32; dd += 2) {
        float v0 = o[dd] * inv_l, v1 = o[dd + 1] * inv_l;
        __nv_bfloat16 h0, h1, l0, l1;
        split1(v0, h0, l0); split1(v1, h1, l1);
        *(__nv_bfloat162*)(out_hi + oidx + dd) = __nv_bfloat162(h0, h1);
        *(__nv_bfloat162*)(out_lo + oidx + dd) = __nv_bfloat162(l0, l1);
    }
}

// ---------------------------------------------------------------------------
// Launch
// ---------------------------------------------------------------------------
extern "C" void kernel_launch(void* const* d_in, const int* in_sizes, int n_in,
                              void* d_out, int out_size)
{
    (void)in_sizes; (void)n_in; (void)out_size;
    const float* x    = (const float*)d_in[0];
    const float* Wqkv = (const float*)d_in[1];
    const float* bqkv = (const float*)d_in[2];
    const float* Wo   = (const float*)d_in[3];
    const float* bo   = (const float*)d_in[4];
    float* out = (float*)d_out;

    float* qkv_p; __nv_bfloat16 *xhi, *xlo, *w1hi, *w1lo, *w2hi, *w2lo, *ahi, *alo;
    cudaGetSymbolAddress((void**)&qkv_p, g_qkv);
    cudaGetSymbolAddress((void**)&xhi, g_xhi);  cudaGetSymbolAddress((void**)&xlo, g_xlo);
    cudaGetSymbolAddress((void**)&w1hi, g_w1hi); cudaGetSymbolAddress((void**)&w1lo, g_w1lo);
    cudaGetSymbolAddress((void**)&w2hi, g_w2hi); cudaGetSymbolAddress((void**)&w2lo, g_w2lo);
    cudaGetSymbolAddress((void**)&ahi, g_ahi);  cudaGetSymbolAddress((void**)&alo, g_alo);

    cudaFuncSetAttribute(gemm_bf16x3,
                         cudaFuncAttributeMaxDynamicSharedMemorySize, GEMM_DYN_SMEM);
    cudaFuncSetAttribute(flash_attn,
                         cudaFuncAttributeMaxDynamicSharedMemorySize, FLASH_SMEM_BYTES);

    // 1) split x into bf16 hi/lo
    {
        int n4 = (M_ * D_) / 4;
        split_f32<<<(n4 + 255) / 256, 256>>>(x, xhi, xlo, n4);
    }
    // 2) transpose+split weights
    transpose_split<<<dim3((3 * D_) / 32, D_ / 32), dim3(32, 8)>>>(Wqkv, w1hi, w1lo, D_, 3 * D_);
    transpose_split<<<dim3(D_ / 32, D_ / 32), dim3(32, 8)>>>(Wo, w2hi, w2lo, D_, D_);

    // 3) qkv = x @ Wqkv + bqkv      [4096, 6144]
    gemm_bf16x3<<<dim3((3 * D_) / 128, M_ / 128), 256, GEMM_DYN_SMEM>>>(
        xhi, xlo, w1hi, w1lo, bqkv, qkv_p, M_, 3 * D_, D_);

    // 4) flash attention -> bf16 hi/lo
    flash_attn<<<dim3(S_ / BQ, H_, B_), 256, FLASH_SMEM_BYTES>>>(qkv_p, ahi, alo);

    // 5) out = attn @ Wo + bo       [4096, 2048]
    gemm_bf16x3<<<dim3(D_ / 128, M_ / 128), 256, GEMM_DYN_SMEM>>>(
        ahi, alo, w2hi, w2lo, bo, out, M_, D_, D_);
}

// round 4
// speedup vs baseline: 2.9711x; 1.8461x over previous
#include <cuda_runtime.h>
#include <cuda_bf16.h>
#include <cstdint>
#include <cstddef>

// ---------------------------------------------------------------------------
// Problem constants
// ---------------------------------------------------------------------------
#define B_  2
#define S_  2048
#define D_  2048
#define H_  16
#define HD_ 128
#define M_  (B_*S_)            // 4096 rows
#define SCALE_ 0.08838834764831845f

// ---------------------------------------------------------------------------
// Scratch (__device__ globals; no allocation allowed)
// ---------------------------------------------------------------------------
__device__ __nv_bfloat16 g_xhi[(size_t)M_ * D_];
__device__ __nv_bfloat16 g_xlo[(size_t)M_ * D_];
__device__ __nv_bfloat16 g_w1hi[(size_t)3 * D_ * D_];   // Wqkv^T [6144,2048]
__device__ __nv_bfloat16 g_w1lo[(size_t)3 * D_ * D_];
__device__ __nv_bfloat16 g_w2hi[(size_t)D_ * D_];       // Wo^T [2048,2048]
__device__ __nv_bfloat16 g_w2lo[(size_t)D_ * D_];
// q/k/v in [B,H,S,HD] bf16 hi/lo (q pre-scaled by 1/sqrt(HD))
__device__ __nv_bfloat16 g_qhi[(size_t)M_ * D_];
__device__ __nv_bfloat16 g_qlo[(size_t)M_ * D_];
__device__ __nv_bfloat16 g_khi[(size_t)M_ * D_];
__device__ __nv_bfloat16 g_klo[(size_t)M_ * D_];
__device__ __nv_bfloat16 g_vhi[(size_t)M_ * D_];
__device__ __nv_bfloat16 g_vlo[(size_t)M_ * D_];
// attention output [B,S,D] bf16 hi/lo
__device__ __nv_bfloat16 g_ahi[(size_t)M_ * D_];
__device__ __nv_bfloat16 g_alo[(size_t)M_ * D_];

// ---------------------------------------------------------------------------
// Portable PTX helpers (virtual arch compute_103: no tcgen05)
// ---------------------------------------------------------------------------
__device__ __forceinline__ uint32_t smem_u32(const void* p) {
    uint32_t a;
    asm("{ .reg .u64 t; cvta.to.shared.u64 t, %1; cvt.u32.u64 %0, t; }"
        : "=r"(a) : "l"(p));
    return a;
}

#define CP16(dst_u32, src_ptr) \
    asm volatile("cp.async.cg.shared.global [%0], [%1], 16;" \
                 :: "r"(dst_u32), "l"(src_ptr) : "memory")
#define CP_COMMIT() asm volatile("cp.async.commit_group;" ::: "memory")
#define CP_WAIT(n)  asm volatile("cp.async.wait_group %0;" :: "n"(n) : "memory")

#define LDSM_X4(r0, r1, r2, r3, addr) \
    asm volatile("ldmatrix.sync.aligned.m8n8.x4.shared.b16 {%0,%1,%2,%3}, [%4];" \
                 : "=r"(r0), "=r"(r1), "=r"(r2), "=r"(r3) : "r"(addr))
#define LDSM_X4T(r0, r1, r2, r3, addr) \
    asm volatile("ldmatrix.sync.aligned.m8n8.x4.trans.shared.b16 {%0,%1,%2,%3}, [%4];" \
                 : "=r"(r0), "=r"(r1), "=r"(r2), "=r"(r3) : "r"(addr))

__device__ __forceinline__ void mma16816(float* d, const uint32_t* a,
                                         const uint32_t* b) {
    asm volatile(
        "mma.sync.aligned.m16n8k16.row.col.f32.bf16.bf16.f32 "
        "{%0,%1,%2,%3}, {%4,%5,%6,%7}, {%8,%9}, {%0,%1,%2,%3};"
        : "+f"(d[0]), "+f"(d[1]), "+f"(d[2]), "+f"(d[3])
        : "r"(a[0]), "r"(a[1]), "r"(a[2]), "r"(a[3]), "r"(b[0]), "r"(b[1]));
}

__device__ __forceinline__ void split1(float v, __nv_bfloat16& h, __nv_bfloat16& l) {
    h = __float2bfloat16(v);
    l = __float2bfloat16(v - __bfloat162float(h));
}

// pack two floats -> bf16x2 hi + bf16x2 lo(residual)
__device__ __forceinline__ void packhl(float x, float y, uint32_t& hp, uint32_t& lp) {
    __nv_bfloat162 hv = __floats2bfloat162_rn(x, y);
    float rx = x - __bfloat162float(__low2bfloat16(hv));
    float ry = y - __bfloat162float(__high2bfloat16(hv));
    __nv_bfloat162 lv = __floats2bfloat162_rn(rx, ry);
    hp = *reinterpret_cast<uint32_t*>(&hv);
    lp = *reinterpret_cast<uint32_t*>(&lv);
}

// ---------------------------------------------------------------------------
// split / transpose-split pre-passes
// ---------------------------------------------------------------------------
__global__ void split_f32(const float* __restrict__ in,
                          __nv_bfloat16* __restrict__ hi,
                          __nv_bfloat16* __restrict__ lo, int n4) {
    int i = blockIdx.x * blockDim.x + threadIdx.x;
    if (i >= n4) return;
    float4 v = *(const float4*)(in + (size_t)i * 4);
    uint32_t h0, h1, l0, l1;
    packhl(v.x, v.y, h0, l0);
    packhl(v.z, v.w, h1, l1);
    uint32_t* hp = (uint32_t*)(hi + (size_t)i * 4);
    uint32_t* lp = (uint32_t*)(lo + (size_t)i * 4);
    hp[0] = h0; hp[1] = h1;
    lp[0] = l0; lp[1] = l1;
}

__global__ void transpose_split(const float* __restrict__ W,
                                __nv_bfloat16* __restrict__ Th,
                                __nv_bfloat16* __restrict__ Tl, int K, int N) {
    __shared__ float t[32][33];
    int n0 = blockIdx.x * 32, k0 = blockIdx.y * 32;
    int tx = threadIdx.x, ty = threadIdx.y;      // (32,8)
    #pragma unroll
    for (int j = 0; j < 32; j += 8)
        t[ty + j][tx] = W[(size_t)(k0 + ty + j) * N + n0 + tx];
    __syncthreads();
    #pragma unroll
    for (int j = 0; j < 32; j += 8) {
        float v = t[tx][ty + j];
        __nv_bfloat16 h, l; split1(v, h, l);
        size_t o = (size_t)(n0 + ty + j) * K + k0 + tx;
        Th[o] = h; Tl[o] = l;
    }
}

// ---------------------------------------------------------------------------
// HMMA bf16x3 GEMM:  C = A @ Bt^T + bias.   BM=BN=128, BK=32, 8 warps,
// 4-stage cp.async pipeline.  mode 0: fp32 C.  mode 1: qkv scatter epilogue.
// ---------------------------------------------------------------------------
#define GBK 32
#define LDSB 80                       // bytes per smem row (32 bf16 + 8 pad)
#define TILEB (128 * LDSB)
#define OFF_AH 0
#define OFF_AL (TILEB)
#define OFF_BH (2 * TILEB)
#define OFF_BL (3 * TILEB)
#define STAGEB (4 * TILEB)            // 40960 B
#define NSTAGE 4
#define GEMM_DYN_SMEM (NSTAGE * STAGEB)

__global__ __launch_bounds__(256, 1) void gemm_bf16x3(
    const __nv_bfloat16* __restrict__ Ah, const __nv_bfloat16* __restrict__ Al,
    const __nv_bfloat16* __restrict__ Bh, const __nv_bfloat16* __restrict__ Bl,
    const float* __restrict__ bias, float* __restrict__ C,
    __nv_bfloat16* __restrict__ qh, __nv_bfloat16* __restrict__ ql,
    __nv_bfloat16* __restrict__ kh, __nv_bfloat16* __restrict__ kl,
    __nv_bfloat16* __restrict__ vh, __nv_bfloat16* __restrict__ vl,
    int M, int N, int K, int mode)
{
    extern __shared__ __align__(128) char sm[];
    const uint32_t sbase = smem_u32(sm);

    const int tid = threadIdx.x;
    const int wid = tid >> 5;
    const int lane = tid & 31;
    const int m0 = blockIdx.y * 128;
    const int n0 = blockIdx.x * 128;
    const int wm = (wid >> 2) * 64;
    const int wn = (wid & 3) * 32;

    const int prow = tid >> 2;
    const int pc = tid & 3;
    auto produce = [&](int stg, int kblk) {
        uint32_t s = sbase + stg * STAGEB;
        #pragma unroll
        for (int hh = 0; hh < 2; hh++) {
            int r = prow + hh * 64;
            uint32_t d = r * LDSB + pc * 16;
            size_t ga = (size_t)(m0 + r) * K + kblk + pc * 8;
            size_t gb = (size_t)(n0 + r) * K + kblk + pc * 8;
            CP16(s + OFF_AH + d, Ah + ga);
            CP16(s + OFF_AL + d, Al + ga);
            CP16(s + OFF_BH + d, Bh + gb);
            CP16(s + OFF_BL + d, Bl + gb);
        }
    };

    float acc[4][4][4];
    #pragma unroll
    for (int i = 0; i < 4; i++)
        #pragma unroll
        for (int j = 0; j < 4; j++)
            #pragma unroll
            for (int r = 0; r < 4; r++) acc[i][j][r] = 0.f;

    const uint32_t a_row = wm + (lane & 15);
    const uint32_t a_kb  = (lane >> 4) * 16;
    const uint32_t b_row = wn + (lane & 7) + ((lane >> 4) & 1) * 8;
    const uint32_t b_kb  = ((lane >> 3) & 1) * 16;

    auto compute = [&](int stg) {
        uint32_t s = sbase + stg * STAGEB;
        #pragma unroll
        for (int ks = 0; ks < 2; ks++) {
            uint32_t ah[4][4], al[4][4], bh2[4][2], bl2[4][2];
            #pragma unroll
            for (int ti = 0; ti < 4; ti++) {
                uint32_t ad = s + (a_row + ti * 16) * LDSB + ks * 32 + a_kb;
                LDSM_X4(ah[ti][0], ah[ti][1], ah[ti][2], ah[ti][3], ad + OFF_AH);
                LDSM_X4(al[ti][0], al[ti][1], al[ti][2], al[ti][3], ad + OFF_AL);
            }
            #pragma unroll
            for (int pj = 0; pj < 2; pj++) {
                uint32_t bd = s + (b_row + pj * 16) * LDSB + ks * 32 + b_kb;
                uint32_t r0, r1, r2, r3;
                LDSM_X4(r0, r1, r2, r3, bd + OFF_BH);
                bh2[pj * 2][0] = r0; bh2[pj * 2][1] = r1;
                bh2[pj * 2 + 1][0] = r2; bh2[pj * 2 + 1][1] = r3;
                LDSM_X4(r0, r1, r2, r3, bd + OFF_BL);
                bl2[pj * 2][0] = r0; bl2[pj * 2][1] = r1;
                bl2[pj * 2 + 1][0] = r2; bl2[pj * 2 + 1][1] = r3;
            }
            #pragma unroll
            for (int ti = 0; ti < 4; ti++)
                #pragma unroll
                for (int tj = 0; tj < 4; tj++) {
                    mma16816(acc[ti][tj], ah[ti], bh2[tj]);
                    mma16816(acc[ti][tj], ah[ti], bl2[tj]);
                    mma16816(acc[ti][tj], al[ti], bh2[tj]);
                }
        }
    };

    const int NK = K / GBK;
    produce(0, 0); CP_COMMIT();
    produce(1, GBK); CP_COMMIT();
    produce(2, 2 * GBK); CP_COMMIT();

    for (int it = 0; it < NK; ++it) {
        CP_WAIT(2);
        __syncthreads();
        compute(it & (NSTAGE - 1));
        if (it + 3 < NK) produce((it + 3) & (NSTAGE - 1), (it + 3) * GBK);
        CP_COMMIT();
    }

    // ---- epilogue ----
    const int er = lane >> 2;
    const int ec = (lane & 3) * 2;
    if (mode == 0) {
        #pragma unroll
        for (int ti = 0; ti < 4; ti++)
            #pragma unroll
            for (int tj = 0; tj < 4; tj++) {
                int col = n0 + wn + tj * 8 + ec;
                float bx = bias[col], by = bias[col + 1];
                int row = m0 + wm + ti * 16 + er;
                float2 v0 = { acc[ti][tj][0] + bx, acc[ti][tj][1] + by };
                float2 v1 = { acc[ti][tj][2] + bx, acc[ti][tj][3] + by };
                *(float2*)(C + (size_t)row * N + col) = v0;
                *(float2*)(C + (size_t)(row + 8) * N + col) = v1;
            }
    } else {
        // scatter into q/k/v [B,H,S,HD] bf16 hi/lo (q scaled)
        #pragma unroll
        for (int ti = 0; ti < 4; ti++)
            #pragma unroll
            for (int tj = 0; tj < 4; tj++) {
                int col = n0 + wn + tj * 8 + ec;
                int hh = col / 384, rem = col % 384;
                int which = rem >> 7, hd = rem & 127;
                __nv_bfloat16* dh = which == 0 ? qh : (which == 1 ? kh : vh);
                __nv_bfloat16* dl = which == 0 ? ql : (which == 1 ? kl : vl);
                float sc = which == 0 ? SCALE_ : 1.0f;
                float bx = bias[col], by = bias[col + 1];
                #pragma unroll
                for (int rr = 0; rr < 2; rr++) {
                    int row = m0 + wm + ti * 16 + er + rr * 8;
                    int bb = row >> 11, ss = row & 2047;
                    size_t off = (((size_t)(bb * H_ + hh)) * S_ + ss) * HD_ + hd;
                    float vx = (acc[ti][tj][rr * 2] + bx) * sc;
                    float vy = (acc[ti][tj][rr * 2 + 1] + by) * sc;
                    uint32_t hp, lp;
                    packhl(vx, vy, hp, lp);
                    *(uint32_t*)(dh + off) = hp;
                    *(uint32_t*)(dl + off) = lp;
                }
            }
    }
}

// ---------------------------------------------------------------------------
// HMMA causal flash attention, bf16x3, FA2-style register softmax.
// BQ=128 (8 warps x 16 rows), BKV=64, HD=128. Double-buffered KV via cp.async.
// ---------------------------------------------------------------------------
#define FROWB 272                      // 128 bf16 + 8 pad = 136 elems
#define FQBYTES (128 * FROWB)          // per Q array
#define FKBYTES (64 * FROWB)           // per K/V array
#define FSTGB (4 * FKBYTES)            // kh,kl,vh,vl
#define FLASH_DYN_SMEM (2 * FQBYTES + 2 * FSTGB)   // 208896 B

__global__ __launch_bounds__(256, 1) void flash_mma(
    const __nv_bfloat16* __restrict__ qh_, const __nv_bfloat16* __restrict__ ql_,
    const __nv_bfloat16* __restrict__ kh_, const __nv_bfloat16* __restrict__ kl_,
    const __nv_bfloat16* __restrict__ vh_, const __nv_bfloat16* __restrict__ vl_,
    __nv_bfloat16* __restrict__ oh_, __nv_bfloat16* __restrict__ ol_)
{
    extern __shared__ __align__(128) char fsm[];
    const uint32_t sb = smem_u32(fsm);
    const int tid = threadIdx.x, wq = tid >> 5, lane = tid & 31;
    const int bi = (int)gridDim.x - 1 - (int)blockIdx.x;   // big blocks first
    const int hh = blockIdx.y, b = blockIdx.z;
    const int q0 = bi * 128;
    const size_t bh = ((size_t)b * H_ + hh) * S_;
    const uint32_t QH = sb, QL = sb + FQBYTES;
    const uint32_t KV0 = sb + 2 * FQBYTES;

    // Q tile load (both hi/lo)
    #pragma unroll
    for (int i = 0; i < 8; i++) {
        int id = tid + i * 256;
        int r = id >> 4, c = id & 15;
        size_t src = (bh + q0 + r) * HD_ + c * 8;
        CP16(QH + r * FROWB + c * 16, qh_ + src);
        CP16(QL + r * FROWB + c * 16, ql_ + src);
    }
    auto produce = [&](int stg, int kt) {
        uint32_t s = KV0 + stg * FSTGB;
        int k0 = kt * 64;
        #pragma unroll
        for (int i = 0; i < 4; i++) {
            int id = tid + i * 256;
            int r = id >> 4, c = id & 15;
            size_t src = (bh + k0 + r) * HD_ + c * 8;
            uint32_t d = r * FROWB + c * 16;
            CP16(s + d, kh_ + src);
            CP16(s + FKBYTES + d, kl_ + src);
            CP16(s + 2 * FKBYTES + d, vh_ + src);
            CP16(s + 3 * FKBYTES + d, vl_ + src);
        }
    };

    float o[16][4];
    #pragma unroll
    for (int j = 0; j < 16; j++)
        #pragma unroll
        for (int r = 0; r < 4; r++) o[j][r] = 0.f;
    float m0 = -1e30f, m1 = -1e30f, l0 = 0.f, l1 = 0.f;

    const int er = lane >> 2, ec2 = (lane & 3) * 2;
    const uint32_t a_row = wq * 16 + (lane & 15);
    const uint32_t a_kb  = (lane >> 4) * 16;
    const uint32_t b_row = (lane & 7) + ((lane >> 4) & 1) * 8;
    const uint32_t b_kb  = ((lane >> 3) & 1) * 16;
    const uint32_t v_row = (lane & 7) + ((lane >> 3) & 1) * 8;
    const uint32_t v_cb  = ((lane >> 4) & 1) * 16;

    const int nkt = 2 * bi + 2;
    produce(0, 0);
    CP_COMMIT();

    for (int kt = 0; kt < nkt; kt++) {
        if (kt + 1 < nkt) { produce((kt + 1) & 1, kt + 1); CP_COMMIT(); CP_WAIT(1); }
        else CP_WAIT(0);
        __syncthreads();
        const uint32_t kb = KV0 + (kt & 1) * FSTGB;

        // ---- phase 1: S = Q K^T (bf16x3) ----
        float s[8][4];
        #pragma unroll
        for (int j = 0; j < 8; j++)
            #pragma unroll
            for (int r = 0; r < 4; r++) s[j][r] = 0.f;

        #pragma unroll
        for (int ks = 0; ks < 8; ks++) {
            uint32_t ah[4], al[4];
            uint32_t qa = QH + a_row * FROWB + ks * 32 + a_kb;
            LDSM_X4(ah[0], ah[1], ah[2], ah[3], qa);
            LDSM_X4(al[0], al[1], al[2], al[3], qa + FQBYTES);
            #pragma unroll
            for (int bj = 0; bj < 4; bj++) {
                uint32_t ka = kb + (bj * 16 + b_row) * FROWB + ks * 32 + b_kb;
                uint32_t h0, h1, h2, h3, g0, g1, g2, g3;
                LDSM_X4(h0, h1, h2, h3, ka);
                LDSM_X4(g0, g1, g2, g3, ka + FKBYTES);
                uint32_t bhi0[2] = {h0, h1}, bhi1[2] = {h2, h3};
                uint32_t blo0[2] = {g0, g1}, blo1[2] = {g2, g3};
                mma16816(s[2 * bj], ah, bhi0);
                mma16816(s[2 * bj], ah, blo0);
                mma16816(s[2 * bj], al, bhi0);
                mma16816(s[2 * bj + 1], ah, bhi1);
                mma16816(s[2 * bj + 1], ah, blo1);
                mma16816(s[2 * bj + 1], al, bhi1);
            }
        }

        // ---- causal mask (only last two tiles) ----
        if (kt >= 2 * bi) {
            int row0 = q0 + wq * 16 + er, row1 = row0 + 8;
            int colb = kt * 64 + ec2;
            #pragma unroll
            for (int j = 0; j < 8; j++) {
                int c0 = colb + j * 8, c1 = c0 + 1;
                if (c0 > row0) s[j][0] = -1e30f;
                if (c1 > row0) s[j][1] = -1e30f;
                if (c0 > row1) s[j][2] = -1e30f;
                if (c1 > row1) s[j][3] = -1e30f;
            }
        }

        // ---- online softmax (rows er / er+8) ----
        float mx0 = -1e30f, mx1 = -1e30f;
        #pragma unroll
        for (int j = 0; j < 8; j++) {
            mx0 = fmaxf(mx0, fmaxf(s[j][0], s[j][1]));
            mx1 = fmaxf(mx1, fmaxf(s[j][2], s[j][3]));
        }
        mx0 = fmaxf(mx0, __shfl_xor_sync(0xffffffffu, mx0, 1));
        mx0 = fmaxf(mx0, __shfl_xor_sync(0xffffffffu, mx0, 2));
        mx1 = fmaxf(mx1, __shfl_xor_sync(0xffffffffu, mx1, 1));
        mx1 = fmaxf(mx1, __shfl_xor_sync(0xffffffffu, mx1, 2));
        float mn0 = fmaxf(m0, mx0), mn1 = fmaxf(m1, mx1);
        float al0 = __expf(m0 - mn0), al1 = __expf(m1 - mn1);
        m0 = mn0; m1 = mn1;
        float sm0 = 0.f, sm1 = 0.f;
        #pragma unroll
        for (int j = 0; j < 8; j++) {
            s[j][0] = __expf(s[j][0] - m0); sm0 += s[j][0];
            s[j][1] = __expf(s[j][1] - m0); sm0 += s[j][1];
            s[j][2] = __expf(s[j][2] - m1); sm1 += s[j][2];
            s[j][3] = __expf(s[j][3] - m1); sm1 += s[j][3];
        }
        sm0 += __shfl_xor_sync(0xffffffffu, sm0, 1);
        sm0 += __shfl_xor_sync(0xffffffffu, sm0, 2);
        sm1 += __shfl_xor_sync(0xffffffffu, sm1, 1);
        sm1 += __shfl_xor_sync(0xffffffffu, sm1, 2);
        l0 = l0 * al0 + sm0;
        l1 = l1 * al1 + sm1;
        #pragma unroll
        for (int j = 0; j < 16; j++) {
            o[j][0] *= al0; o[j][1] *= al0;
            o[j][2] *= al1; o[j][3] *= al1;
        }

        // ---- phase 2: O += P V (bf16x3; V via ldmatrix.trans) ----
        const uint32_t vbase = kb + 2 * FKBYTES;
        #pragma unroll
        for (int ki = 0; ki < 4; ki++) {
            uint32_t ph[4], pl[4];
            packhl(s[2 * ki][0],     s[2 * ki][1],     ph[0], pl[0]);
            packhl(s[2 * ki][2],     s[2 * ki][3],     ph[1], pl[1]);
            packhl(s[2 * ki + 1][0], s[2 * ki + 1][1], ph[2], pl[2]);
            packhl(s[2 * ki + 1][2], s[2 * ki + 1][3], ph[3], pl[3]);
            #pragma unroll
            for (int nj = 0; nj < 8; nj++) {
                uint32_t va = vbase + (ki * 16 + v_row) * FROWB + nj * 32 + v_cb;
                uint32_t h0, h1, h2, h3, g0, g1, g2, g3;
                LDSM_X4T(h0, h1, h2, h3, va);
                LDSM_X4T(g0, g1, g2, g3, va + FKBYTES);
                uint32_t vh0[2] = {h0, h1}, vh1[2] = {h2, h3};
                uint32_t vl0[2] = {g0, g1}, vl1[2] = {g2, g3};
                mma16816(o[2 * nj], ph, vh0);
                mma16816(o[2 * nj], ph, vl0);
                mma16816(o[2 * nj], pl, vh0);
                mma16816(o[2 * nj + 1], ph, vh1);
                mma16816(o[2 * nj + 1], ph, vl1);
                mma16816(o[2 * nj + 1], pl, vh1);
            }
        }
        __syncthreads();   // protect KV buffer before next produce overwrites
    }

    // ---- epilogue: normalize + bf16 hi/lo write ----
    float il0 = 1.f / l0, il1 = 1.f / l1;
    int row0 = q0 + wq * 16 + er;
    #pragma unroll
    for (int j = 0; j < 16; j++) {
        int col = hh * 128 + j * 8 + ec2;
        uint32_t hp, lp;
        packhl(o[j][0] * il0, o[j][1] * il0, hp, lp);
        size_t off0 = ((size_t)b * S_ + row0) * D_ + col;
        *(uint32_t*)(oh_ + off0) = hp;
        *(uint32_t*)(ol_ + off0) = lp;
        packhl(o[j][2] * il1, o[j][3] * il1, hp, lp);
        size_t off1 = ((size_t)b * S_ + row0 + 8) * D_ + col;
        *(uint32_t*)(oh_ + off1) = hp;
        *(uint32_t*)(ol_ + off1) = lp;
    }
}

// ---------------------------------------------------------------------------
// Launch
// ---------------------------------------------------------------------------
extern "C" void kernel_launch(void* const* d_in, const int* in_sizes, int n_in,
                              void* d_out, int out_size)
{
    (void)in_sizes; (void)n_in; (void)out_size;
    const float* x    = (const float*)d_in[0];
    const float* Wqkv = (const float*)d_in[1];
    const float* bqkv = (const float*)d_in[2];
    const float* Wo   = (const float*)d_in[3];
    const float* bo   = (const float*)d_in[4];
    float* out = (float*)d_out;

    __nv_bfloat16 *xhi, *xlo, *w1hi, *w1lo, *w2hi, *w2lo;
    __nv_bfloat16 *qhi, *qlo, *khi, *klo, *vhi, *vlo, *ahi, *alo;
    cudaGetSymbolAddress((void**)&xhi, g_xhi);   cudaGetSymbolAddress((void**)&xlo, g_xlo);
    cudaGetSymbolAddress((void**)&w1hi, g_w1hi); cudaGetSymbolAddress((void**)&w1lo, g_w1lo);
    cudaGetSymbolAddress((void**)&w2hi, g_w2hi); cudaGetSymbolAddress((void**)&w2lo, g_w2lo);
    cudaGetSymbolAddress((void**)&qhi, g_qhi);   cudaGetSymbolAddress((void**)&qlo, g_qlo);
    cudaGetSymbolAddress((void**)&khi, g_khi);   cudaGetSymbolAddress((void**)&klo, g_klo);
    cudaGetSymbolAddress((void**)&vhi, g_vhi);   cudaGetSymbolAddress((void**)&vlo, g_vlo);
    cudaGetSymbolAddress((void**)&ahi, g_ahi);   cudaGetSymbolAddress((void**)&alo, g_alo);

    cudaFuncSetAttribute(gemm_bf16x3,
                         cudaFuncAttributeMaxDynamicSharedMemorySize, GEMM_DYN_SMEM);
    cudaFuncSetAttribute(flash_mma,
                         cudaFuncAttributeMaxDynamicSharedMemorySize, FLASH_DYN_SMEM);

    // 1) split x
    {
        int n4 = (M_ * D_) / 4;
        split_f32<<<(n4 + 255) / 256, 256>>>(x, xhi, xlo, n4);
    }
    // 2) transpose+split weights
    transpose_split<<<dim3((3 * D_) / 32, D_ / 32), dim3(32, 8)>>>(Wqkv, w1hi, w1lo, D_, 3 * D_);
    transpose_split<<<dim3(D_ / 32, D_ / 32), dim3(32, 8)>>>(Wo, w2hi, w2lo, D_, D_);

    // 3) QKV GEMM with fused bias+scale+split+scatter epilogue
    gemm_bf16x3<<<dim3((3 * D_) / 128, M_ / 128), 256, GEMM_DYN_SMEM>>>(
        xhi, xlo, w1hi, w1lo, bqkv, nullptr,
        qhi, qlo, khi, klo, vhi, vlo, M_, 3 * D_, D_, 1);

    // 4) HMMA flash attention
    flash_mma<<<dim3(S_ / 128, H_, B_), 256, FLASH_DYN_SMEM>>>(
        qhi, qlo, khi, klo, vhi, vlo, ahi, alo);

    // 5) out = attn @ Wo + bo
    gemm_bf16x3<<<dim3(D_ / 128, M_ / 128), 256, GEMM_DYN_SMEM>>>(
        ahi, alo, w2hi, w2lo, bo, out,
        nullptr, nullptr, nullptr, nullptr, nullptr, nullptr, M_, D_, D_, 0);
}

// round 5
// speedup vs baseline: 3.4659x; 1.1665x over previous
#include <cuda_runtime.h>
#include <cuda_bf16.h>
#include <cstdint>
#include <cstddef>

// ---------------------------------------------------------------------------
// Problem constants
// ---------------------------------------------------------------------------
#define B_  2
#define S_  2048
#define D_  2048
#define H_  16
#define HD_ 128
#define M_  (B_*S_)            // 4096 rows
#define SCALE_ 0.08838834764831845f

// ---------------------------------------------------------------------------
// Scratch (__device__ globals; no allocation allowed)
// ---------------------------------------------------------------------------
__device__ __nv_bfloat16 g_xhi[(size_t)M_ * D_];
__device__ __nv_bfloat16 g_xlo[(size_t)M_ * D_];
__device__ __nv_bfloat16 g_w1hi[(size_t)3 * D_ * D_];   // Wqkv^T [6144,2048]
__device__ __nv_bfloat16 g_w1lo[(size_t)3 * D_ * D_];
__device__ __nv_bfloat16 g_w2hi[(size_t)D_ * D_];       // Wo^T [2048,2048]
__device__ __nv_bfloat16 g_w2lo[(size_t)D_ * D_];
// q/k/v in [B,H,S,HD] bf16 hi/lo (q pre-scaled by 1/sqrt(HD))
__device__ __nv_bfloat16 g_qhi[(size_t)M_ * D_];
__device__ __nv_bfloat16 g_qlo[(size_t)M_ * D_];
__device__ __nv_bfloat16 g_khi[(size_t)M_ * D_];
__device__ __nv_bfloat16 g_klo[(size_t)M_ * D_];
__device__ __nv_bfloat16 g_vhi[(size_t)M_ * D_];
__device__ __nv_bfloat16 g_vlo[(size_t)M_ * D_];
// attention output [B,S,D] bf16 hi/lo
__device__ __nv_bfloat16 g_ahi[(size_t)M_ * D_];
__device__ __nv_bfloat16 g_alo[(size_t)M_ * D_];

// ---------------------------------------------------------------------------
// Portable PTX helpers (virtual arch compute_103: no tcgen05)
// ---------------------------------------------------------------------------
__device__ __forceinline__ uint32_t smem_u32(const void* p) {
    uint32_t a;
    asm("{ .reg .u64 t; cvta.to.shared.u64 t, %1; cvt.u32.u64 %0, t; }"
        : "=r"(a) : "l"(p));
    return a;
}

#define CP16(dst_u32, src_ptr) \
    asm volatile("cp.async.cg.shared.global [%0], [%1], 16;" \
                 :: "r"(dst_u32), "l"(src_ptr) : "memory")
#define CP_COMMIT() asm volatile("cp.async.commit_group;" ::: "memory")
#define CP_WAIT(n)  asm volatile("cp.async.wait_group %0;" :: "n"(n) : "memory")

#define LDSM_X4(r0, r1, r2, r3, addr) \
    asm volatile("ldmatrix.sync.aligned.m8n8.x4.shared.b16 {%0,%1,%2,%3}, [%4];" \
                 : "=r"(r0), "=r"(r1), "=r"(r2), "=r"(r3) : "r"(addr))
#define LDSM_X4T(r0, r1, r2, r3, addr) \
    asm volatile("ldmatrix.sync.aligned.m8n8.x4.trans.shared.b16 {%0,%1,%2,%3}, [%4];" \
                 : "=r"(r0), "=r"(r1), "=r"(r2), "=r"(r3) : "r"(addr))

__device__ __forceinline__ void mma16816(float* d, const uint32_t* a,
                                         const uint32_t* b) {
    asm volatile(
        "mma.sync.aligned.m16n8k16.row.col.f32.bf16.bf16.f32 "
        "{%0,%1,%2,%3}, {%4,%5,%6,%7}, {%8,%9}, {%0,%1,%2,%3};"
        : "+f"(d[0]), "+f"(d[1]), "+f"(d[2]), "+f"(d[3])
        : "r"(a[0]), "r"(a[1]), "r"(a[2]), "r"(a[3]), "r"(b[0]), "r"(b[1]));
}

__device__ __forceinline__ void split1(float v, __nv_bfloat16& h, __nv_bfloat16& l) {
    h = __float2bfloat16(v);
    l = __float2bfloat16(v - __bfloat162float(h));
}

// pack two floats -> bf16x2 hi + bf16x2 lo(residual)
__device__ __forceinline__ void packhl(float x, float y, uint32_t& hp, uint32_t& lp) {
    __nv_bfloat162 hv = __floats2bfloat162_rn(x, y);
    float rx = x - __bfloat162float(__low2bfloat16(hv));
    float ry = y - __bfloat162float(__high2bfloat16(hv));
    __nv_bfloat162 lv = __floats2bfloat162_rn(rx, ry);
    hp = *reinterpret_cast<uint32_t*>(&hv);
    lp = *reinterpret_cast<uint32_t*>(&lv);
}

// ---------------------------------------------------------------------------
// split / transpose-split pre-passes
// ---------------------------------------------------------------------------
__global__ void split_f32(const float* __restrict__ in,
                          __nv_bfloat16* __restrict__ hi,
                          __nv_bfloat16* __restrict__ lo, int n4) {
    int i = blockIdx.x * blockDim.x + threadIdx.x;
    if (i >= n4) return;
    float4 v = *(const float4*)(in + (size_t)i * 4);
    uint32_t h0, h1, l0, l1;
    packhl(v.x, v.y, h0, l0);
    packhl(v.z, v.w, h1, l1);
    uint32_t* hp = (uint32_t*)(hi + (size_t)i * 4);
    uint32_t* lp = (uint32_t*)(lo + (size_t)i * 4);
    hp[0] = h0; hp[1] = h1;
    lp[0] = l0; lp[1] = l1;
}

__global__ void transpose_split(const float* __restrict__ W,
                                __nv_bfloat16* __restrict__ Th,
                                __nv_bfloat16* __restrict__ Tl, int K, int N) {
    __shared__ float t[32][33];
    int n0 = blockIdx.x * 32, k0 = blockIdx.y * 32;
    int tx = threadIdx.x, ty = threadIdx.y;      // (32,8)
    #pragma unroll
    for (int j = 0; j < 32; j += 8)
        t[ty + j][tx] = W[(size_t)(k0 + ty + j) * N + n0 + tx];
    __syncthreads();
    #pragma unroll
    for (int j = 0; j < 32; j += 8) {
        float v = t[tx][ty + j];
        __nv_bfloat16 h, l; split1(v, h, l);
        size_t o = (size_t)(n0 + ty + j) * K + k0 + tx;
        Th[o] = h; Tl[o] = l;
    }
}

// ---------------------------------------------------------------------------
// HMMA bf16x3 GEMM:  C = A @ Bt^T + bias.   BM=128, BN=256, BK=32,
// 8 warps (2x4), warp tile 64x64, 4-stage cp.async, XOR-swizzled smem.
// mode 0: fp32 C.  mode 1: qkv scatter epilogue.
// ---------------------------------------------------------------------------
#define GBK 32
// 64B rows, chunk swizzle: chunk ^= (row>>1)&3  (conflict-free LDSM + stores)
#define GSWZ(r, c) ((uint32_t)(r) * 64u + ((((uint32_t)(c) ^ (((uint32_t)(r) >> 1) & 3u))) << 4))
#define OFF_AH 0
#define OFF_AL 8192                   // 128 rows * 64B
#define OFF_BH 16384
#define OFF_BL 32768                  // B: 256 rows * 64B
#define STAGEB 49152
#define NSTAGE 4
#define GEMM_DYN_SMEM (NSTAGE * STAGEB)   // 196608

__global__ __launch_bounds__(256, 1) void gemm_bf16x3(
    const __nv_bfloat16* __restrict__ Ah, const __nv_bfloat16* __restrict__ Al,
    const __nv_bfloat16* __restrict__ Bh, const __nv_bfloat16* __restrict__ Bl,
    const float* __restrict__ bias, float* __restrict__ C,
    __nv_bfloat16* __restrict__ qh, __nv_bfloat16* __restrict__ ql,
    __nv_bfloat16* __restrict__ kh, __nv_bfloat16* __restrict__ kl,
    __nv_bfloat16* __restrict__ vh, __nv_bfloat16* __restrict__ vl,
    int M, int N, int K, int mode)
{
    extern __shared__ __align__(128) char sm[];
    const uint32_t sbase = smem_u32(sm);

    const int tid = threadIdx.x;
    const int wid = tid >> 5;
    const int lane = tid & 31;
    const int m0 = blockIdx.y * 128;
    const int n0 = blockIdx.x * 256;
    const int wm = (wid >> 2) * 64;      // 0 / 64
    const int wn = (wid & 3) * 64;       // 0/64/128/192

    // ---- producer: 12 cp.async of 16B per thread per stage ----
    const int tr = tid >> 2;             // 0..63
    const int pc = tid & 3;              // chunk 0..3
    auto produce = [&](int stg, int kblk) {
        uint32_t s = sbase + stg * STAGEB;
        #pragma unroll
        for (int hh = 0; hh < 2; hh++) {
            int r = tr + hh * 64;
            uint32_t d = GSWZ(r, pc);
            size_t ga = (size_t)(m0 + r) * K + kblk + pc * 8;
            CP16(s + OFF_AH + d, Ah + ga);
            CP16(s + OFF_AL + d, Al + ga);
        }
        #pragma unroll
        for (int hh = 0; hh < 4; hh++) {
            int r = tr + hh * 64;
            uint32_t d = GSWZ(r, pc);
            size_t gb = (size_t)(n0 + r) * K + kblk + pc * 8;
            CP16(s + OFF_BH + d, Bh + gb);
            CP16(s + OFF_BL + d, Bl + gb);
        }
    };

    float acc[4][8][4];
    #pragma unroll
    for (int i = 0; i < 4; i++)
        #pragma unroll
        for (int j = 0; j < 8; j++)
            #pragma unroll
            for (int r = 0; r < 4; r++) acc[i][j][r] = 0.f;

    auto compute = [&](int stg) {
        uint32_t s = sbase + stg * STAGEB;
        #pragma unroll
        for (int ks = 0; ks < 2; ks++) {
            uint32_t ah[4][4], al[4][4];
            #pragma unroll
            for (int ti = 0; ti < 4; ti++) {
                uint32_t r = wm + ti * 16 + (lane & 15);
                uint32_t ch = ks * 2 + (lane >> 4);
                uint32_t ad = s + GSWZ(r, ch);
                LDSM_X4(ah[ti][0], ah[ti][1], ah[ti][2], ah[ti][3], ad + OFF_AH);
                LDSM_X4(al[ti][0], al[ti][1], al[ti][2], al[ti][3], ad + OFF_AL);
            }
            #pragma unroll
            for (int pj = 0; pj < 4; pj++) {
                uint32_t r = wn + pj * 16 + (lane & 7) + ((lane >> 4) & 1) * 8;
                uint32_t ch = ks * 2 + ((lane >> 3) & 1);
                uint32_t bd = s + GSWZ(r, ch);
                uint32_t h0, h1, h2, h3, g0, g1, g2, g3;
                LDSM_X4(h0, h1, h2, h3, bd + OFF_BH);
                LDSM_X4(g0, g1, g2, g3, bd + OFF_BL);
                uint32_t bh0[2] = {h0, h1}, bh1[2] = {h2, h3};
                uint32_t bl0[2] = {g0, g1}, bl1[2] = {g2, g3};
                #pragma unroll
                for (int ti = 0; ti < 4; ti++) {
                    mma16816(acc[ti][2 * pj],     ah[ti], bh0);
                    mma16816(acc[ti][2 * pj],     ah[ti], bl0);
                    mma16816(acc[ti][2 * pj],     al[ti], bh0);
                    mma16816(acc[ti][2 * pj + 1], ah[ti], bh1);
                    mma16816(acc[ti][2 * pj + 1], ah[ti], bl1);
                    mma16816(acc[ti][2 * pj + 1], al[ti], bh1);
                }
            }
        }
    };

    const int NK = K / GBK;
    produce(0, 0); CP_COMMIT();
    produce(1, GBK); CP_COMMIT();
    produce(2, 2 * GBK); CP_COMMIT();

    for (int it = 0; it < NK; ++it) {
        CP_WAIT(2);
        __syncthreads();
        compute(it & (NSTAGE - 1));
        if (it + 3 < NK) produce((it + 3) & (NSTAGE - 1), (it + 3) * GBK);
        CP_COMMIT();
    }

    // ---- epilogue ----
    const int er = lane >> 2;
    const int ec = (lane & 3) * 2;
    if (mode == 0) {
        #pragma unroll
        for (int tj = 0; tj < 8; tj++) {
            int col = n0 + wn + tj * 8 + ec;
            float bx = bias[col], by = bias[col + 1];
            #pragma unroll
            for (int ti = 0; ti < 4; ti++) {
                int row = m0 + wm + ti * 16 + er;
                float2 v0 = { acc[ti][tj][0] + bx, acc[ti][tj][1] + by };
                float2 v1 = { acc[ti][tj][2] + bx, acc[ti][tj][3] + by };
                *(float2*)(C + (size_t)row * N + col) = v0;
                *(float2*)(C + (size_t)(row + 8) * N + col) = v1;
            }
        }
    } else {
        // scatter into q/k/v [B,H,S,HD] bf16 hi/lo (q scaled)
        #pragma unroll
        for (int tj = 0; tj < 8; tj++) {
            int col = n0 + wn + tj * 8 + ec;
            int hh = col / 384, rem = col % 384;
            int which = rem >> 7, hd = rem & 127;
            __nv_bfloat16* dh = which == 0 ? qh : (which == 1 ? kh : vh);
            __nv_bfloat16* dl = which == 0 ? ql : (which == 1 ? kl : vl);
            float sc = which == 0 ? SCALE_ : 1.0f;
            float bx = bias[col], by = bias[col + 1];
            #pragma unroll
            for (int ti = 0; ti < 4; ti++) {
                #pragma unroll
                for (int rr = 0; rr < 2; rr++) {
                    int row = m0 + wm + ti * 16 + er + rr * 8;
                    int bb = row >> 11, ss = row & 2047;
                    size_t off = (((size_t)(bb * H_ + hh)) * S_ + ss) * HD_ + hd;
                    float vx = (acc[ti][tj][rr * 2] + bx) * sc;
                    float vy = (acc[ti][tj][rr * 2 + 1] + by) * sc;
                    uint32_t hp, lp;
                    packhl(vx, vy, hp, lp);
                    *(uint32_t*)(dh + off) = hp;
                    *(uint32_t*)(dl + off) = lp;
                }
            }
        }
    }
}

// ---------------------------------------------------------------------------
// HMMA causal flash attention, bf16x3, FA2-style register softmax.
// BQ=128 (8 warps x 16 rows), BKV=64, HD=128. Double-buffered KV via cp.async.
// ---------------------------------------------------------------------------
#define FROWB 272                      // 128 bf16 + 8 pad = 136 elems
#define FQBYTES (128 * FROWB)          // per Q array
#define FKBYTES (64 * FROWB)           // per K/V array
#define FSTGB (4 * FKBYTES)            // kh,kl,vh,vl
#define FLASH_DYN_SMEM (2 * FQBYTES + 2 * FSTGB)   // 208896 B

__global__ __launch_bounds__(256, 1) void flash_mma(
    const __nv_bfloat16* __restrict__ qh_, const __nv_bfloat16* __restrict__ ql_,
    const __nv_bfloat16* __restrict__ kh_, const __nv_bfloat16* __restrict__ kl_,
    const __nv_bfloat16* __restrict__ vh_, const __nv_bfloat16* __restrict__ vl_,
    __nv_bfloat16* __restrict__ oh_, __nv_bfloat16* __restrict__ ol_)
{
    extern __shared__ __align__(128) char fsm[];
    const uint32_t sb = smem_u32(fsm);
    const int tid = threadIdx.x, wq = tid >> 5, lane = tid & 31;
    const int bi = (int)gridDim.x - 1 - (int)blockIdx.x;   // big blocks first
    const int hh = blockIdx.y, b = blockIdx.z;
    const int q0 = bi * 128;
    const size_t bh = ((size_t)b * H_ + hh) * S_;
    const uint32_t QH = sb, QL = sb + FQBYTES;
    const uint32_t KV0 = sb + 2 * FQBYTES;

    // Q tile load (both hi/lo)
    #pragma unroll
    for (int i = 0; i < 8; i++) {
        int id = tid + i * 256;
        int r = id >> 4, c = id & 15;
        size_t src = (bh + q0 + r) * HD_ + c * 8;
        CP16(QH + r * FROWB + c * 16, qh_ + src);
        CP16(QL + r * FROWB + c * 16, ql_ + src);
    }
    auto produce = [&](int stg, int kt) {
        uint32_t s = KV0 + stg * FSTGB;
        int k0 = kt * 64;
        #pragma unroll
        for (int i = 0; i < 4; i++) {
            int id = tid + i * 256;
            int r = id >> 4, c = id & 15;
            size_t src = (bh + k0 + r) * HD_ + c * 8;
            uint32_t d = r * FROWB + c * 16;
            CP16(s + d, kh_ + src);
            CP16(s + FKBYTES + d, kl_ + src);
            CP16(s + 2 * FKBYTES + d, vh_ + src);
            CP16(s + 3 * FKBYTES + d, vl_ + src);
        }
    };

    float o[16][4];
    #pragma unroll
    for (int j = 0; j < 16; j++)
        #pragma unroll
        for (int r = 0; r < 4; r++) o[j][r] = 0.f;
    float m0 = -1e30f, m1 = -1e30f, l0 = 0.f, l1 = 0.f;

    const int er = lane >> 2, ec2 = (lane & 3) * 2;
    const uint32_t a_row = wq * 16 + (lane & 15);
    const uint32_t a_kb  = (lane >> 4) * 16;
    const uint32_t b_row = (lane & 7) + ((lane >> 4) & 1) * 8;
    const uint32_t b_kb  = ((lane >> 3) & 1) * 16;
    const uint32_t v_row = (lane & 7) + ((lane >> 3) & 1) * 8;
    const uint32_t v_cb  = ((lane >> 4) & 1) * 16;

    const int nkt = 2 * bi + 2;
    produce(0, 0);
    CP_COMMIT();

    for (int kt = 0; kt < nkt; kt++) {
        if (kt + 1 < nkt) { produce((kt + 1) & 1, kt + 1); CP_COMMIT(); CP_WAIT(1); }
        else CP_WAIT(0);
        __syncthreads();
        const uint32_t kb = KV0 + (kt & 1) * FSTGB;

        // ---- phase 1: S = Q K^T (bf16x3) ----
        float s[8][4];
        #pragma unroll
        for (int j = 0; j < 8; j++)
            #pragma unroll
            for (int r = 0; r < 4; r++) s[j][r] = 0.f;

        #pragma unroll
        for (int ks = 0; ks < 8; ks++) {
            uint32_t ah[4], al[4];
            uint32_t qa = QH + a_row * FROWB + ks * 32 + a_kb;
            LDSM_X4(ah[0], ah[1], ah[2], ah[3], qa);
            LDSM_X4(al[0], al[1], al[2], al[3], qa + FQBYTES);
            #pragma unroll
            for (int bj = 0; bj < 4; bj++) {
                uint32_t ka = kb + (bj * 16 + b_row) * FROWB + ks * 32 + b_kb;
                uint32_t h0, h1, h2, h3, g0, g1, g2, g3;
                LDSM_X4(h0, h1, h2, h3, ka);
                LDSM_X4(g0, g1, g2, g3, ka + FKBYTES);
                uint32_t bhi0[2] = {h0, h1}, bhi1[2] = {h2, h3};
                uint32_t blo0[2] = {g0, g1}, blo1[2] = {g2, g3};
                mma16816(s[2 * bj], ah, bhi0);
                mma16816(s[2 * bj], ah, blo0);
                mma16816(s[2 * bj], al, bhi0);
                mma16816(s[2 * bj + 1], ah, bhi1);
                mma16816(s[2 * bj + 1], ah, blo1);
                mma16816(s[2 * bj + 1], al, bhi1);
            }
        }

        // ---- causal mask (only last two tiles) ----
        if (kt >= 2 * bi) {
            int row0 = q0 + wq * 16 + er, row1 = row0 + 8;
            int colb = kt * 64 + ec2;
            #pragma unroll
            for (int j = 0; j < 8; j++) {
                int c0 = colb + j * 8, c1 = c0 + 1;
                if (c0 > row0) s[j][0] = -1e30f;
                if (c1 > row0) s[j][1] = -1e30f;
                if (c0 > row1) s[j][2] = -1e30f;
                if (c1 > row1) s[j][3] = -1e30f;
            }
        }

        // ---- online softmax (rows er / er+8) ----
        float mx0 = -1e30f, mx1 = -1e30f;
        #pragma unroll
        for (int j = 0; j < 8; j++) {
            mx0 = fmaxf(mx0, fmaxf(s[j][0], s[j][1]));
            mx1 = fmaxf(mx1, fmaxf(s[j][2], s[j][3]));
        }
        mx0 = fmaxf(mx0, __shfl_xor_sync(0xffffffffu, mx0, 1));
        mx0 = fmaxf(mx0, __shfl_xor_sync(0xffffffffu, mx0, 2));
        mx1 = fmaxf(mx1, __shfl_xor_sync(0xffffffffu, mx1, 1));
        mx1 = fmaxf(mx1, __shfl_xor_sync(0xffffffffu, mx1, 2));
        float mn0 = fmaxf(m0, mx0), mn1 = fmaxf(m1, mx1);
        float al0 = __expf(m0 - mn0), al1 = __expf(m1 - mn1);
        m0 = mn0; m1 = mn1;
        float sm0 = 0.f, sm1 = 0.f;
        #pragma unroll
        for (int j = 0; j < 8; j++) {
            s[j][0] = __expf(s[j][0] - m0); sm0 += s[j][0];
            s[j][1] = __expf(s[j][1] - m0); sm0 += s[j][1];
            s[j][2] = __expf(s[j][2] - m1); sm1 += s[j][2];
            s[j][3] = __expf(s[j][3] - m1); sm1 += s[j][3];
        }
        sm0 += __shfl_xor_sync(0xffffffffu, sm0, 1);
        sm0 += __shfl_xor_sync(0xffffffffu, sm0, 2);
        sm1 += __shfl_xor_sync(0xffffffffu, sm1, 1);
        sm1 += __shfl_xor_sync(0xffffffffu, sm1, 2);
        l0 = l0 * al0 + sm0;
        l1 = l1 * al1 + sm1;
        #pragma unroll
        for (int j = 0; j < 16; j++) {
            o[j][0] *= al0; o[j][1] *= al0;
            o[j][2] *= al1; o[j][3] *= al1;
        }

        // ---- phase 2: O += P V (bf16x3; V via ldmatrix.trans) ----
        const uint32_t vbase = kb + 2 * FKBYTES;
        #pragma unroll
        for (int ki = 0; ki < 4; ki++) {
            uint32_t ph[4], pl[4];
            packhl(s[2 * ki][0],     s[2 * ki][1],     ph[0], pl[0]);
            packhl(s[2 * ki][2],     s[2 * ki][3],     ph[1], pl[1]);
            packhl(s[2 * ki + 1][0], s[2 * ki + 1][1], ph[2], pl[2]);
            packhl(s[2 * ki + 1][2], s[2 * ki + 1][3], ph[3], pl[3]);
            #pragma unroll
            for (int nj = 0; nj < 8; nj++) {
                uint32_t va = vbase + (ki * 16 + v_row) * FROWB + nj * 32 + v_cb;
                uint32_t h0, h1, h2, h3, g0, g1, g2, g3;
                LDSM_X4T(h0, h1, h2, h3, va);
                LDSM_X4T(g0, g1, g2, g3, va + FKBYTES);
                uint32_t vh0[2] = {h0, h1}, vh1[2] = {h2, h3};
                uint32_t vl0[2] = {g0, g1}, vl1[2] = {g2, g3};
                mma16816(o[2 * nj], ph, vh0);
                mma16816(o[2 * nj], ph, vl0);
                mma16816(o[2 * nj], pl, vh0);
                mma16816(o[2 * nj + 1], ph, vh1);
                mma16816(o[2 * nj + 1], ph, vl1);
                mma16816(o[2 * nj + 1], pl, vh1);
            }
        }
        __syncthreads();   // protect KV buffer before next produce overwrites
    }

    // ---- epilogue: normalize + bf16 hi/lo write ----
    float il0 = 1.f / l0, il1 = 1.f / l1;
    int row0 = q0 + wq * 16 + er;
    #pragma unroll
    for (int j = 0; j < 16; j++) {
        int col = hh * 128 + j * 8 + ec2;
        uint32_t hp, lp;
        packhl(o[j][0] * il0, o[j][1] * il0, hp, lp);
        size_t off0 = ((size_t)b * S_ + row0) * D_ + col;
        *(uint32_t*)(oh_ + off0) = hp;
        *(uint32_t*)(ol_ + off0) = lp;
        packhl(o[j][2] * il1, o[j][3] * il1, hp, lp);
        size_t off1 = ((size_t)b * S_ + row0 + 8) * D_ + col;
        *(uint32_t*)(oh_ + off1) = hp;
        *(uint32_t*)(ol_ + off1) = lp;
    }
}

// ---------------------------------------------------------------------------
// Launch
// ---------------------------------------------------------------------------
extern "C" void kernel_launch(void* const* d_in, const int* in_sizes, int n_in,
                              void* d_out, int out_size)
{
    (void)in_sizes; (void)n_in; (void)out_size;
    const float* x    = (const float*)d_in[0];
    const float* Wqkv = (const float*)d_in[1];
    const float* bqkv = (const float*)d_in[2];
    const float* Wo   = (const float*)d_in[3];
    const float* bo   = (const float*)d_in[4];
    float* out = (float*)d_out;

    __nv_bfloat16 *xhi, *xlo, *w1hi, *w1lo, *w2hi, *w2lo;
    __nv_bfloat16 *qhi, *qlo, *khi, *klo, *vhi, *vlo, *ahi, *alo;
    cudaGetSymbolAddress((void**)&xhi, g_xhi);   cudaGetSymbolAddress((void**)&xlo, g_xlo);
    cudaGetSymbolAddress((void**)&w1hi, g_w1hi); cudaGetSymbolAddress((void**)&w1lo, g_w1lo);
    cudaGetSymbolAddress((void**)&w2hi, g_w2hi); cudaGetSymbolAddress((void**)&w2lo, g_w2lo);
    cudaGetSymbolAddress((void**)&qhi, g_qhi);   cudaGetSymbolAddress((void**)&qlo, g_qlo);
    cudaGetSymbolAddress((void**)&khi, g_khi);   cudaGetSymbolAddress((void**)&klo, g_klo);
    cudaGetSymbolAddress((void**)&vhi, g_vhi);   cudaGetSymbolAddress((void**)&vlo, g_vlo);
    cudaGetSymbolAddress((void**)&ahi, g_ahi);   cudaGetSymbolAddress((void**)&alo, g_alo);

    cudaFuncSetAttribute(gemm_bf16x3,
                         cudaFuncAttributeMaxDynamicSharedMemorySize, GEMM_DYN_SMEM);
    cudaFuncSetAttribute(flash_mma,
                         cudaFuncAttributeMaxDynamicSharedMemorySize, FLASH_DYN_SMEM);

    // 1) split x
    {
        int n4 = (M_ * D_) / 4;
        split_f32<<<(n4 + 255) / 256, 256>>>(x, xhi, xlo, n4);
    }
    // 2) transpose+split weights
    transpose_split<<<dim3((3 * D_) / 32, D_ / 32), dim3(32, 8)>>>(Wqkv, w1hi, w1lo, D_, 3 * D_);
    transpose_split<<<dim3(D_ / 32, D_ / 32), dim3(32, 8)>>>(Wo, w2hi, w2lo, D_, D_);

    // 3) QKV GEMM with fused bias+scale+split+scatter epilogue
    gemm_bf16x3<<<dim3((3 * D_) / 256, M_ / 128), 256, GEMM_DYN_SMEM>>>(
        xhi, xlo, w1hi, w1lo, bqkv, nullptr,
        qhi, qlo, khi, klo, vhi, vlo, M_, 3 * D_, D_, 1);

    // 4) HMMA flash attention
    flash_mma<<<dim3(S_ / 128, H_, B_), 256, FLASH_DYN_SMEM>>>(
        qhi, qlo, khi, klo, vhi, vlo, ahi, alo);

    // 5) out = attn @ Wo + bo
    gemm_bf16x3<<<dim3(D_ / 256, M_ / 128), 256, GEMM_DYN_SMEM>>>(
        ahi, alo, w2hi, w2lo, bo, out,
        nullptr, nullptr, nullptr, nullptr, nullptr, nullptr, M_, D_, D_, 0);
}